// round 1
// baseline (speedup 1.0000x reference)
#include <cuda_runtime.h>
#include <math.h>

#define N_TX   100000
#define N_ADDR 100000
#define E_NUM  1000000
#define H_NUM  4
#define D_DIM  16
#define HID    64
#define G_NUM  128

// ---------------- scratch (device globals; no allocation allowed) ----------------
__device__ float g_A_addr[65 * 64];   // combined proj for addr nodes
__device__ float g_b_addr[64];
__device__ float g_U_tx[65 * 4];      // combined proj straight to alpha_dst for tx nodes
__device__ float g_v_tx[4];
__device__ float g_z_addr[N_ADDR * 64];
__device__ float g_alpha_src[N_ADDR * 4];
__device__ float g_alpha_dst[N_TX * 4];
__device__ float g_m[N_TX * 4];       // segment max per (tx node, head)
__device__ float g_s[N_TX * 4];       // segment exp-sum
__device__ float g_out[N_TX * 64];    // unnormalized weighted feature sum
__device__ float g_pool[G_NUM * 64];
__device__ float g_cnt[G_NUM];

__device__ __forceinline__ void atomicMaxF(float* addr, float v) {
    if (v >= 0.f) atomicMax((int*)addr, __float_as_int(v));
    else          atomicMin((unsigned int*)addr, __float_as_uint(v));
}

__device__ __forceinline__ float leaky(float x) { return x > 0.f ? x : 0.2f * x; }

// ---------------- kernel 1: fold weights -----------------------------------------
// A_addr = Wp_addr @ Wh_addr ; b_addr = bp_addr @ Wh_addr + bh_addr
// U_tx[k][h] = sum_j Wp_tx[k][j] * ( sum_d Wh_tx[j][h*16+d] * att_dst_at[h][d] )
// v_tx[h]   = sum_j bp_tx[j]*t[j][h] + sum_d bh_tx[h*16+d]*att_dst_at[h][d]
__global__ void prep_kernel(const float* __restrict__ Wp_tx, const float* __restrict__ bp_tx,
                            const float* __restrict__ Wp_addr, const float* __restrict__ bp_addr,
                            const float* __restrict__ Wh_tx, const float* __restrict__ bh_tx,
                            const float* __restrict__ Wh_addr, const float* __restrict__ bh_addr,
                            const float* __restrict__ att_dst_at) {
    __shared__ float t[64 * 4];
    int tid = threadIdx.x;
    // phase 1: t
    for (int idx = tid; idx < 64 * 4; idx += blockDim.x) {
        int j = idx >> 2, h = idx & 3;
        float s = 0.f;
        for (int d = 0; d < 16; d++) s += Wh_tx[j * 64 + h * 16 + d] * att_dst_at[h * 16 + d];
        t[j * 4 + h] = s;
    }
    __syncthreads();
    // U_tx
    for (int idx = tid; idx < 65 * 4; idx += blockDim.x) {
        int k = idx >> 2, h = idx & 3;
        float s = 0.f;
        for (int j = 0; j < 64; j++) s += Wp_tx[k * 64 + j] * t[j * 4 + h];
        g_U_tx[k * 4 + h] = s;
    }
    // v_tx
    if (tid < 4) {
        int h = tid;
        float s = 0.f;
        for (int j = 0; j < 64; j++) s += bp_tx[j] * t[j * 4 + h];
        for (int d = 0; d < 16; d++) s += bh_tx[h * 16 + d] * att_dst_at[h * 16 + d];
        g_v_tx[h] = s;
    }
    // A_addr
    for (int idx = tid; idx < 65 * 64; idx += blockDim.x) {
        int k = idx >> 6, c = idx & 63;
        float s = 0.f;
        for (int j = 0; j < 64; j++) s += Wp_addr[k * 64 + j] * Wh_addr[j * 64 + c];
        g_A_addr[idx] = s;
    }
    // b_addr
    for (int c = tid; c < 64; c += blockDim.x) {
        float s = bh_addr[c];
        for (int j = 0; j < 64; j++) s += bp_addr[j] * Wh_addr[j * 64 + c];
        g_b_addr[c] = s;
    }
}

// ---------------- kernel 2: init scratch ------------------------------------------
__global__ void init_kernel() {
    int i = blockIdx.x * blockDim.x + threadIdx.x;
    if (i < N_TX * 64) g_out[i] = 0.f;
    if (i < N_TX * 4) { g_m[i] = -INFINITY; g_s[i] = 0.f; }
    if (i < G_NUM * 64) g_pool[i] = 0.f;
    if (i < G_NUM) g_cnt[i] = 0.f;
}

// ---------------- kernel 3: alpha_dst for tx nodes (warp per node) ----------------
__global__ void tx_alpha_kernel(const float* __restrict__ x_tx) {
    __shared__ float U[65 * 4];
    __shared__ float v[4];
    int tid = threadIdx.x;
    for (int i = tid; i < 65 * 4; i += blockDim.x) U[i] = g_U_tx[i];
    if (tid < 4) v[tid] = g_v_tx[tid];
    __syncthreads();
    int warp = (blockIdx.x * blockDim.x + tid) >> 5;
    int lane = tid & 31;
    if (warp >= N_TX) return;
    const float* xr = x_tx + (long long)warp * 65;
    float x0 = xr[lane];
    float x1 = xr[32 + lane];
    float x2 = (lane == 0) ? xr[64] : 0.f;
#pragma unroll
    for (int h = 0; h < 4; h++) {
        float p = x0 * U[lane * 4 + h] + x1 * U[(32 + lane) * 4 + h] + x2 * U[64 * 4 + h];
#pragma unroll
        for (int off = 16; off > 0; off >>= 1) p += __shfl_xor_sync(0xffffffffu, p, off);
        if (lane == h) g_alpha_dst[warp * 4 + h] = p + v[h];
    }
}

// ---------------- kernel 4: z_addr GEMM + alpha_src epilogue ----------------------
// blockDim = (64,4); each (block,y) = one addr node
__global__ void addr_gemm_kernel(const float* __restrict__ x_addr,
                                 const float* __restrict__ att_src_at) {
    int col = threadIdx.x;
    int node = blockIdx.x * 4 + threadIdx.y;
    if (node >= N_ADDR) return;
    const float* xr = x_addr + (long long)node * 65;
    float acc = g_b_addr[col];
#pragma unroll
    for (int k = 0; k < 65; k++) acc += xr[k] * g_A_addr[k * 64 + col];
    g_z_addr[node * 64 + col] = acc;
    // alpha_src: reduce acc*att over 16-lane groups (col = h*16+d, att flattened [h][d])
    float p = acc * att_src_at[col];
#pragma unroll
    for (int off = 8; off > 0; off >>= 1) p += __shfl_xor_sync(0xffffffffu, p, off);
    if ((col & 15) == 0) g_alpha_src[node * 4 + (col >> 4)] = p;
}

// ---------------- kernel 5: edge pass 1 (segment max) -----------------------------
__global__ void edge_max_kernel(const int* __restrict__ edge) {
    int e = blockIdx.x * blockDim.x + threadIdx.x;
    if (e >= E_NUM) return;
    int src = edge[e];          // addr node
    int dst = edge[E_NUM + e];  // tx node
    const float4 as = *(const float4*)&g_alpha_src[src * 4];
    const float4 ad = *(const float4*)&g_alpha_dst[dst * 4];
    atomicMaxF(&g_m[dst * 4 + 0], leaky(as.x + ad.x));
    atomicMaxF(&g_m[dst * 4 + 1], leaky(as.y + ad.y));
    atomicMaxF(&g_m[dst * 4 + 2], leaky(as.z + ad.z));
    atomicMaxF(&g_m[dst * 4 + 3], leaky(as.w + ad.w));
}

// ---------------- kernel 6: edge pass 2 (exp-sum + weighted scatter) --------------
// warp per edge; scatters UNNORMALIZED e*z, node pass divides by s later.
__global__ void edge_scatter_kernel(const int* __restrict__ edge) {
    int gtid = blockIdx.x * blockDim.x + threadIdx.x;
    int warp = gtid >> 5;
    int lane = gtid & 31;
    if (warp >= E_NUM) return;
    int src = edge[warp];
    int dst = edge[E_NUM + warp];
    float ev = 0.f;
    if (lane < 4) {
        float a = leaky(g_alpha_src[src * 4 + lane] + g_alpha_dst[dst * 4 + lane]);
        ev = __expf(a - g_m[dst * 4 + lane]);
        atomicAdd(&g_s[dst * 4 + lane], ev);
    }
    float e_lo = __shfl_sync(0xffffffffu, ev, lane >> 4);        // head for channel lane
    float e_hi = __shfl_sync(0xffffffffu, ev, 2 + (lane >> 4));  // head for channel lane+32
    float z0 = g_z_addr[src * 64 + lane];
    float z1 = g_z_addr[src * 64 + 32 + lane];
    atomicAdd(&g_out[dst * 64 + lane], e_lo * z0);
    atomicAdd(&g_out[dst * 64 + 32 + lane], e_hi * z1);
}

// ---------------- kernel 7: normalize + relu + sorted-batch pool ------------------
// blockDim=(64,4); each (block,y) handles a contiguous 256-node run; batch_tx is
// sorted, so register run-accumulation flushes ~2-3 atomics per thread.
__global__ void pool_kernel(const int* __restrict__ batch_tx) {
    int c = threadIdx.x;
    int n0 = blockIdx.x * 1024 + threadIdx.y * 256;
    int n1 = n0 + 256; if (n1 > N_TX) n1 = N_TX;
    float acc = 0.f, cacc = 0.f;
    int cur = -1;
    for (int n = n0; n < n1; n++) {
        int b = batch_tx[n];
        if (b != cur) {
            if (cur >= 0) {
                atomicAdd(&g_pool[cur * 64 + c], acc);
                if (c == 0) atomicAdd(&g_cnt[cur], cacc);
            }
            acc = 0.f; cacc = 0.f; cur = b;
        }
        float s4 = g_s[n * 4 + (c >> 4)];
        float v = g_out[n * 64 + c] / (s4 + 1e-16f);
        acc += fmaxf(v, 0.f);
        cacc += 1.0f;
    }
    if (cur >= 0) {
        atomicAdd(&g_pool[cur * 64 + c], acc);
        if (c == 0) atomicAdd(&g_cnt[cur], cacc);
    }
}

// ---------------- kernel 8: classifier MLP ----------------------------------------
__global__ void final_kernel(const float* __restrict__ W_c1, const float* __restrict__ b_c1,
                             const float* __restrict__ W_c2, const float* __restrict__ b_c2,
                             float* __restrict__ out) {
    int g = threadIdx.x;
    if (g >= G_NUM) return;
    float inv = 1.0f / fmaxf(g_cnt[g], 1.0f);
    float feat[64];
#pragma unroll
    for (int c = 0; c < 64; c++) feat[c] = g_pool[g * 64 + c] * inv;
    float o = b_c2[0];
#pragma unroll 4
    for (int j = 0; j < 32; j++) {
        float hsum = b_c1[j];
#pragma unroll
        for (int c = 0; c < 64; c++) hsum += feat[c] * W_c1[c * 32 + j];
        o += fmaxf(hsum, 0.f) * W_c2[j];
    }
    out[g] = o;
}

// ---------------- launch ----------------------------------------------------------
extern "C" void kernel_launch(void* const* d_in, const int* in_sizes, int n_in,
                              void* d_out, int out_size) {
    const float* x_tx       = (const float*)d_in[0];
    const float* x_addr     = (const float*)d_in[1];
    const float* W_proj_tx  = (const float*)d_in[2];
    const float* b_proj_tx  = (const float*)d_in[3];
    const float* W_proj_addr= (const float*)d_in[4];
    const float* b_proj_addr= (const float*)d_in[5];
    const float* W_han_tx   = (const float*)d_in[6];
    const float* b_han_tx   = (const float*)d_in[7];
    const float* W_han_addr = (const float*)d_in[8];
    const float* b_han_addr = (const float*)d_in[9];
    // d_in[10], d_in[11]: att_src_ta / att_dst_ta  (dead: out_addr unused)
    const float* att_src_at = (const float*)d_in[12];
    const float* att_dst_at = (const float*)d_in[13];
    // d_in[14..16]: W_k, b_k, q (dead: single-metapath softmax == 1)
    const float* W_c1       = (const float*)d_in[17];
    const float* b_c1       = (const float*)d_in[18];
    const float* W_c2       = (const float*)d_in[19];
    const float* b_c2       = (const float*)d_in[20];
    // d_in[21]: edge_ta (dead)
    const int*   edge_at    = (const int*)d_in[22];
    const int*   batch_tx   = (const int*)d_in[23];
    float* out = (float*)d_out;

    prep_kernel<<<1, 256>>>(W_proj_tx, b_proj_tx, W_proj_addr, b_proj_addr,
                            W_han_tx, b_han_tx, W_han_addr, b_han_addr, att_dst_at);
    init_kernel<<<(N_TX * 64 + 255) / 256, 256>>>();
    tx_alpha_kernel<<<(N_TX * 32 + 255) / 256, 256>>>(x_tx);
    {
        dim3 blk(64, 4);
        addr_gemm_kernel<<<(N_ADDR + 3) / 4, blk>>>(x_addr, att_src_at);
    }
    edge_max_kernel<<<(E_NUM + 255) / 256, 256>>>(edge_at);
    edge_scatter_kernel<<<(E_NUM * 32 + 255) / 256, 256>>>(edge_at);
    {
        dim3 blk(64, 4);
        pool_kernel<<<(N_TX + 1023) / 1024, blk>>>(batch_tx);
    }
    final_kernel<<<1, 128>>>(W_c1, b_c1, W_c2, b_c2, out);
}

// round 2
// speedup vs baseline: 1.2017x; 1.2017x over previous
#include <cuda_runtime.h>
#include <math.h>

#define N_TX   100000
#define N_ADDR 100000
#define E_NUM  1000000
#define HID    64
#define G_NUM  128

// ---------------- scratch (device globals; no allocation allowed) ----------------
__device__ float g_A_addr[65 * 64];   // combined proj for addr nodes
__device__ float g_b_addr[64];
__device__ float g_U_tx[65 * 4];      // combined proj straight to alpha_dst for tx nodes
__device__ float g_v_tx[4];
__device__ float g_z_addr[N_ADDR * 64];
__device__ float g_alpha_src[N_ADDR * 4];
__device__ float g_alpha_dst[N_TX * 4];
__device__ float g_s[N_TX * 4];       // segment exp-sum
__device__ float g_out[N_TX * 64];    // unnormalized weighted feature sum
__device__ float g_pool[G_NUM * 64];
__device__ float g_cnt[G_NUM];

__device__ __forceinline__ float leaky(float x) { return x > 0.f ? x : 0.2f * x; }

__device__ __forceinline__ void red_add_v4(float* addr, float4 v) {
    asm volatile("red.global.add.v4.f32 [%0], {%1, %2, %3, %4};"
                 :: "l"(addr), "f"(v.x), "f"(v.y), "f"(v.z), "f"(v.w)
                 : "memory");
}

// ---------------- kernel 1: fold weights -----------------------------------------
__global__ void prep_kernel(const float* __restrict__ Wp_tx, const float* __restrict__ bp_tx,
                            const float* __restrict__ Wp_addr, const float* __restrict__ bp_addr,
                            const float* __restrict__ Wh_tx, const float* __restrict__ bh_tx,
                            const float* __restrict__ Wh_addr, const float* __restrict__ bh_addr,
                            const float* __restrict__ att_dst_at) {
    __shared__ float t[64 * 4];
    int tid = threadIdx.x;
    for (int idx = tid; idx < 64 * 4; idx += blockDim.x) {
        int j = idx >> 2, h = idx & 3;
        float s = 0.f;
        for (int d = 0; d < 16; d++) s += Wh_tx[j * 64 + h * 16 + d] * att_dst_at[h * 16 + d];
        t[j * 4 + h] = s;
    }
    __syncthreads();
    for (int idx = tid; idx < 65 * 4; idx += blockDim.x) {
        int k = idx >> 2, h = idx & 3;
        float s = 0.f;
        for (int j = 0; j < 64; j++) s += Wp_tx[k * 64 + j] * t[j * 4 + h];
        g_U_tx[k * 4 + h] = s;
    }
    if (tid < 4) {
        int h = tid;
        float s = 0.f;
        for (int j = 0; j < 64; j++) s += bp_tx[j] * t[j * 4 + h];
        for (int d = 0; d < 16; d++) s += bh_tx[h * 16 + d] * att_dst_at[h * 16 + d];
        g_v_tx[h] = s;
    }
    for (int idx = tid; idx < 65 * 64; idx += blockDim.x) {
        int k = idx >> 6, c = idx & 63;
        float s = 0.f;
        for (int j = 0; j < 64; j++) s += Wp_addr[k * 64 + j] * Wh_addr[j * 64 + c];
        g_A_addr[idx] = s;
    }
    for (int c = tid; c < 64; c += blockDim.x) {
        float s = bh_addr[c];
        for (int j = 0; j < 64; j++) s += bp_addr[j] * Wh_addr[j * 64 + c];
        g_b_addr[c] = s;
    }
}

// ---------------- kernel 2: init scratch ------------------------------------------
__global__ void init_kernel() {
    int i = blockIdx.x * blockDim.x + threadIdx.x;
    if (i < N_TX * 64) g_out[i] = 0.f;
    if (i < N_TX * 4) g_s[i] = 0.f;
    if (i < G_NUM * 64) g_pool[i] = 0.f;
    if (i < G_NUM) g_cnt[i] = 0.f;
}

// ---------------- kernel 3: alpha_dst for tx nodes (warp per node) ----------------
__global__ void tx_alpha_kernel(const float* __restrict__ x_tx) {
    __shared__ float U[65 * 4];
    __shared__ float v[4];
    int tid = threadIdx.x;
    for (int i = tid; i < 65 * 4; i += blockDim.x) U[i] = g_U_tx[i];
    if (tid < 4) v[tid] = g_v_tx[tid];
    __syncthreads();
    int warp = (blockIdx.x * blockDim.x + tid) >> 5;
    int lane = tid & 31;
    if (warp >= N_TX) return;
    const float* xr = x_tx + (long long)warp * 65;
    float x0 = xr[lane];
    float x1 = xr[32 + lane];
    float x2 = (lane == 0) ? xr[64] : 0.f;
#pragma unroll
    for (int h = 0; h < 4; h++) {
        float p = x0 * U[lane * 4 + h] + x1 * U[(32 + lane) * 4 + h] + x2 * U[64 * 4 + h];
#pragma unroll
        for (int off = 16; off > 0; off >>= 1) p += __shfl_xor_sync(0xffffffffu, p, off);
        if (lane == h) g_alpha_dst[warp * 4 + h] = p + v[h];
    }
}

// ---------------- kernel 4: z_addr GEMM + alpha_src epilogue (smem-tiled) ---------
// 256 threads; 64 nodes per block; A transposed into smem [col][k] (pad 68).
__global__ void addr_gemm_kernel(const float* __restrict__ x_addr,
                                 const float* __restrict__ att_src_at) {
    __shared__ float As[64 * 68];
    __shared__ float xs[4][68];
    __shared__ float bs[64];
    __shared__ float att[64];
    int tid = threadIdx.x;
    for (int i = tid; i < 65 * 64; i += 256) {
        int k = i >> 6, c = i & 63;
        As[c * 68 + k] = g_A_addr[i];
    }
    for (int i = tid; i < 64 * 3; i += 256) {    // zero-pad k=65..67
        int c = i / 3, k = 65 + (i % 3);
        As[c * 68 + k] = 0.f;
    }
    if (tid < 64) { bs[tid] = g_b_addr[tid]; att[tid] = att_src_at[tid]; }
    if (tid < 12) xs[tid / 3][65 + (tid % 3)] = 0.f;   // zero-pad x rows
    __syncthreads();

    int col = tid & 63, y = tid >> 6;
    int node0 = blockIdx.x * 64;
#pragma unroll 1
    for (int t = 0; t < 16; t++) {
        int node = node0 + t * 4 + y;
        bool valid = node < N_ADDR;
        if (valid) {
            xs[y][col] = x_addr[(long long)node * 65 + col];
            if (col == 0) xs[y][64] = x_addr[(long long)node * 65 + 64];
        }
        __syncthreads();
        if (valid) {
            float acc = bs[col];
            const float4* xv4 = (const float4*)xs[y];
            const float4* av4 = (const float4*)&As[col * 68];
#pragma unroll
            for (int k4 = 0; k4 < 17; k4++) {
                float4 xv = xv4[k4], av = av4[k4];
                acc += xv.x * av.x + xv.y * av.y + xv.z * av.z + xv.w * av.w;
            }
            g_z_addr[node * 64 + col] = acc;
            float p = acc * att[col];
#pragma unroll
            for (int off = 8; off > 0; off >>= 1) p += __shfl_xor_sync(0xffffffffu, p, off);
            if ((col & 15) == 0) g_alpha_src[node * 4 + (col >> 4)] = p;
        }
        __syncthreads();
    }
}

// ---------------- kernel 5: edge pass (exp + vectorized scatter) -------------------
// 8 threads per edge. No max-subtraction: logits are O(1), softmax shift-invariant.
// 17 red.global.add.v4.f32 per edge instead of 68 scalar atomics.
__global__ void edge_scatter_kernel(const int* __restrict__ edge) {
    int gtid = blockIdx.x * blockDim.x + threadIdx.x;
    int eid = gtid >> 3;
    int sub = gtid & 7;
    if (eid >= E_NUM) return;   // grid sized exactly: never taken, keeps warps full
    int src = __ldg(&edge[eid]);
    int dst = __ldg(&edge[E_NUM + eid]);
    float ev = 0.f;
    if (sub < 4) {
        float a = __ldg(&g_alpha_src[src * 4 + sub]) + __ldg(&g_alpha_dst[dst * 4 + sub]);
        ev = __expf(leaky(a));
    }
    unsigned lane = threadIdx.x & 31;
    unsigned base = lane & ~7u;
    float e0 = __shfl_sync(0xffffffffu, ev, base + 0);
    float e1 = __shfl_sync(0xffffffffu, ev, base + 1);
    float e2 = __shfl_sync(0xffffffffu, ev, base + 2);
    float e3 = __shfl_sync(0xffffffffu, ev, base + 3);
    if (sub == 0) red_add_v4(&g_s[dst * 4], make_float4(e0, e1, e2, e3));
    // channels [8*sub, 8*sub+8) all belong to head sub>>1
    float e = __shfl_sync(0xffffffffu, ev, base + (sub >> 1));
    const float4* zp = (const float4*)&g_z_addr[src * 64 + sub * 8];
    float4 z0 = zp[0], z1 = zp[1];
    red_add_v4(&g_out[dst * 64 + sub * 8],
               make_float4(e * z0.x, e * z0.y, e * z0.z, e * z0.w));
    red_add_v4(&g_out[dst * 64 + sub * 8 + 4],
               make_float4(e * z1.x, e * z1.y, e * z1.z, e * z1.w));
}

// ---------------- kernel 6: normalize + relu + sorted-batch pool ------------------
__global__ void pool_kernel(const int* __restrict__ batch_tx) {
    int c = threadIdx.x;
    int n0 = blockIdx.x * 1024 + threadIdx.y * 256;
    int n1 = n0 + 256; if (n1 > N_TX) n1 = N_TX;
    float acc = 0.f, cacc = 0.f;
    int cur = -1;
    for (int n = n0; n < n1; n++) {
        int b = batch_tx[n];
        if (b != cur) {
            if (cur >= 0) {
                atomicAdd(&g_pool[cur * 64 + c], acc);
                if (c == 0) atomicAdd(&g_cnt[cur], cacc);
            }
            acc = 0.f; cacc = 0.f; cur = b;
        }
        float s4 = g_s[n * 4 + (c >> 4)];
        float v = g_out[n * 64 + c] / (s4 + 1e-16f);
        acc += fmaxf(v, 0.f);
        cacc += 1.0f;
    }
    if (cur >= 0) {
        atomicAdd(&g_pool[cur * 64 + c], acc);
        if (c == 0) atomicAdd(&g_cnt[cur], cacc);
    }
}

// ---------------- kernel 7: classifier MLP ----------------------------------------
__global__ void final_kernel(const float* __restrict__ W_c1, const float* __restrict__ b_c1,
                             const float* __restrict__ W_c2, const float* __restrict__ b_c2,
                             float* __restrict__ out) {
    int g = threadIdx.x;
    if (g >= G_NUM) return;
    float inv = 1.0f / fmaxf(g_cnt[g], 1.0f);
    float feat[64];
#pragma unroll
    for (int c = 0; c < 64; c++) feat[c] = g_pool[g * 64 + c] * inv;
    float o = b_c2[0];
#pragma unroll 4
    for (int j = 0; j < 32; j++) {
        float hsum = b_c1[j];
#pragma unroll
        for (int c = 0; c < 64; c++) hsum += feat[c] * W_c1[c * 32 + j];
        o += fmaxf(hsum, 0.f) * W_c2[j];
    }
    out[g] = o;
}

// ---------------- launch ----------------------------------------------------------
extern "C" void kernel_launch(void* const* d_in, const int* in_sizes, int n_in,
                              void* d_out, int out_size) {
    const float* x_tx       = (const float*)d_in[0];
    const float* x_addr     = (const float*)d_in[1];
    const float* W_proj_tx  = (const float*)d_in[2];
    const float* b_proj_tx  = (const float*)d_in[3];
    const float* W_proj_addr= (const float*)d_in[4];
    const float* b_proj_addr= (const float*)d_in[5];
    const float* W_han_tx   = (const float*)d_in[6];
    const float* b_han_tx   = (const float*)d_in[7];
    const float* W_han_addr = (const float*)d_in[8];
    const float* b_han_addr = (const float*)d_in[9];
    const float* att_src_at = (const float*)d_in[12];
    const float* att_dst_at = (const float*)d_in[13];
    const float* W_c1       = (const float*)d_in[17];
    const float* b_c1       = (const float*)d_in[18];
    const float* W_c2       = (const float*)d_in[19];
    const float* b_c2       = (const float*)d_in[20];
    const int*   edge_at    = (const int*)d_in[22];
    const int*   batch_tx   = (const int*)d_in[23];
    float* out = (float*)d_out;

    prep_kernel<<<1, 256>>>(W_proj_tx, b_proj_tx, W_proj_addr, b_proj_addr,
                            W_han_tx, b_han_tx, W_han_addr, b_han_addr, att_dst_at);
    init_kernel<<<(N_TX * 64 + 255) / 256, 256>>>();
    tx_alpha_kernel<<<(N_TX * 32 + 255) / 256, 256>>>(x_tx);
    addr_gemm_kernel<<<(N_ADDR + 63) / 64, 256>>>(x_addr, att_src_at);
    edge_scatter_kernel<<<(E_NUM * 8) / 256, 256>>>(edge_at);
    {
        dim3 blk(64, 4);
        pool_kernel<<<(N_TX + 1023) / 1024, blk>>>(batch_tx);
    }
    final_kernel<<<1, 128>>>(W_c1, b_c1, W_c2, b_c2, out);
}